// round 13
// baseline (speedup 1.0000x reference)
#include <cuda_runtime.h>
#include <cuda_fp16.h>
#include <math.h>
#include <stdint.h>

#define NPTS      524288
#define GRIDSZ    512
#define NC        36
#define KIN       129
#define K1PAD     136
#define HID       256
#define NOUT      129
#define TB        64
#define NTHREADS  256

// ---- smem byte layout (per CTA, 2 CTAs/SM) ----
#define BY_W1   0
#define BY_W2   0
#define BY_A1   76032
#define BY_A2   76032
#define BY_HB1  109824      // half2 table: 100*b1, 128 entries (512 B)
#define BY_B2S  110848      // f32 b2, padded to 144
#define SMEM_BYTES 111424

#define SA1_B 272         // A1/W1 row stride bytes; 272%128=16 -> ldsm conflict-free
#define SA2_B 528         // A2/W2 row stride bytes; 528%128=16 -> ldsm conflict-free
#define N2PAD 144

__device__ __align__(16) __half g_planesTh[3*GRIDSZ*GRIDSZ*NC]; // [i][y][x][c] fp16
__device__ __align__(16) __half g_linesTh[3*GRIDSZ*NC];         // [i][l][c] fp16
__device__ __align__(16) __half g_W1h[256*136];   // [n][k], fp16, zero-padded k>=129
__device__ __align__(16) __half g_W2h[N2PAD*264]; // [n][k], fp16, zero-padded

// ================= prep kernels =================
__global__ void __launch_bounds__(256) transpose_planes(const float* __restrict__ planes) {
    __shared__ float tile[8][32*37];
    int wid = threadIdx.x >> 5, lane = threadIdx.x & 31;
    int cell0 = (blockIdx.x * 8 + wid) * 32;
    int i = cell0 / (GRIDSZ*GRIDSZ);
    int rem = cell0 - i*GRIDSZ*GRIDSZ;
    int y = rem >> 9, x0 = rem & (GRIDSZ-1);
    const float* src = planes + (long)i*NC*GRIDSZ*GRIDSZ + (long)y*GRIDSZ + x0 + lane;
    float* t = tile[wid];
    #pragma unroll
    for (int c = 0; c < NC; c++) t[lane*37 + c] = src[(long)c*GRIDSZ*GRIDSZ];
    __syncwarp();
    __half2* dst = (__half2*)(g_planesTh + (long)cell0 * NC);
    #pragma unroll
    for (int k = 0; k < 18; k++) {
        int h2i = k*32 + lane;
        int e0 = h2i*2;
        int cc = e0 / NC, c = e0 - cc*NC;
        dst[h2i] = __floats2half2_rn(t[cc*37+c], t[cc*37+c+1]);
    }
}

__global__ void transpose_lines(const float* __restrict__ lines) {
    int t2 = blockIdx.x * blockDim.x + threadIdx.x;
    if (t2 < 3*GRIDSZ) {
        int j = t2 & (GRIDSZ-1), i = t2 >> 9;
        __half* dst = g_linesTh + t2*NC;
        const float* src = lines + (long)i*NC*GRIDSZ + j;
        #pragma unroll
        for (int c = 0; c < NC; c++) dst[c] = __float2half_rn(src[(long)c*GRIDSZ]);
    }
}

__global__ void pack_weights_kernel(const float* __restrict__ W1, const float* __restrict__ W2) {
    int idx = blockIdx.x * blockDim.x + threadIdx.x;
    const int T1 = 256*136;
    const int T2 = N2PAD*264;
    if (idx < T1) {
        int n = idx / 136, k = idx - n*136;
        g_W1h[idx] = (k < KIN) ? __float2half_rn(W1[k*HID + n]) : __float2half_rn(0.f);
    } else if (idx < T1 + T2) {
        int j = idx - T1;
        int n = j / 264, k = j - n*264;
        float v = (k < 256 && n < NOUT) ? W2[k*NOUT + n] : 0.f;
        g_W2h[j] = __float2half_rn(v);
    }
}

// ================= mma / ldmatrix helpers =================
__device__ __forceinline__ void mma_f16_k16(float c[4], unsigned a0, unsigned a1,
                                            unsigned a2, unsigned a3,
                                            unsigned b0, unsigned b1) {
    asm volatile(
        "mma.sync.aligned.m16n8k16.row.col.f32.f16.f16.f32 "
        "{%0,%1,%2,%3},{%4,%5,%6,%7},{%8,%9},{%0,%1,%2,%3};"
        : "+f"(c[0]), "+f"(c[1]), "+f"(c[2]), "+f"(c[3])
        : "r"(a0), "r"(a1), "r"(a2), "r"(a3), "r"(b0), "r"(b1));
}
__device__ __forceinline__ void mma_f16_k8(float c[4], unsigned a0, unsigned a1, unsigned b0) {
    asm volatile(
        "mma.sync.aligned.m16n8k8.row.col.f32.f16.f16.f32 "
        "{%0,%1,%2,%3},{%4,%5},{%6},{%0,%1,%2,%3};"
        : "+f"(c[0]), "+f"(c[1]), "+f"(c[2]), "+f"(c[3])
        : "r"(a0), "r"(a1), "r"(b0));
}
__device__ __forceinline__ void ldsm_x4(unsigned& r0, unsigned& r1, unsigned& r2, unsigned& r3,
                                        uint32_t a) {
    asm volatile("ldmatrix.sync.aligned.m8n8.x4.shared.b16 {%0,%1,%2,%3}, [%4];"
                 : "=r"(r0), "=r"(r1), "=r"(r2), "=r"(r3) : "r"(a));
}
__device__ __forceinline__ void ldsm_x2(unsigned& r0, unsigned& r1, uint32_t a) {
    asm volatile("ldmatrix.sync.aligned.m8n8.x2.shared.b16 {%0,%1}, [%2];"
                 : "=r"(r0), "=r"(r1) : "r"(a));
}

// half2 softplus of y/100 where y = 100*z + hb (hb = 100*b1)
__device__ __forceinline__ __half2 softplus2(__half2 z, __half2 hb) {
    const __half2 h100  = __float2half2_rn(100.f);
    const __half2 one2  = __float2half2_rn(1.f);
    const __half2 zero2 = __float2half2_rn(0.f);
    const __half2 c001  = __float2half2_rn(0.01f);
    __half2 y = __hfma2(z, h100, hb);
    __half2 e = h2exp(__hneg2(__habs2(y)));
    __half2 l = h2log(__hadd2(one2, e));
    __half2 m = __hmax2(y, zero2);
    return __hmul2(__hadd2(m, l), c001);
}

__device__ __forceinline__ void cp16(uint32_t dst, const void* src) {
    asm volatile("cp.async.cg.shared.global [%0], [%1], 16;" :: "r"(dst), "l"(src));
}
__device__ __forceinline__ void cp_commit() { asm volatile("cp.async.commit_group;"); }
__device__ __forceinline__ void cp_wait0()  { asm volatile("cp.async.wait_group 0;" ::: "memory"); }

// ================= main fused kernel (2 CTAs/SM) =================
__global__ void __launch_bounds__(NTHREADS, 2)
tensosdf_main(const float* __restrict__ xyz,
              const float* __restrict__ b1, const float* __restrict__ b2,
              float* __restrict__ out) {
    extern __shared__ char smem[];
    const uint32_t smem_u32 = (uint32_t)__cvta_generic_to_shared(smem);
    __half2* hb1 = (__half2*)(smem + BY_HB1);
    float* b2s = (float*)(smem + BY_B2S);

    const int tid  = threadIdx.x;
    const int lane = tid & 31;
    const int warp = tid >> 5;            // 0..7
    const int pbase = blockIdx.x * TB;
    const int g = lane >> 2;
    const int t = lane & 3;

    // ---- biases ----
    if (tid < 128)
        hb1[tid] = __floats2half2_rn(100.f*b1[2*tid], 100.f*b1[2*tid+1]);
    if (tid < N2PAD) b2s[tid] = (tid < NOUT) ? b2[tid] : 0.f;

    // ---- stage W1 image (69632 B = 4352 x 16B), overlaps gather ----
    for (int idx = tid; idx < 4352; idx += NTHREADS)
        cp16(smem_u32 + BY_W1 + (uint32_t)idx*16u, (const char*)g_W1h + idx*16);
    cp_commit();

    // ---- gather: warp handles 8 points, fp16 tables, writes fp16 A1 ----
    {
        const unsigned FULL = 0xffffffffu;
        float vload = 0.f;
        int base3 = (pbase + warp*8)*3;
        if (lane < 24) vload = xyz[base3 + lane];

        const int i_of = (lane < 9) ? 0 : ((lane < 18) ? 1 : 2);
        const int cj = (lane - i_of*9) * 4;
        const bool act = lane < 27;
        const int fcol = i_of*NC + cj;
        const int pcol = 108 + lane;

        #pragma unroll
        for (int pi = 0; pi < 8; pi++) {
            float x0 = __shfl_sync(FULL, vload, pi*3+0);
            float x1 = __shfl_sync(FULL, vload, pi*3+1);
            float x2 = __shfl_sync(FULL, vload, pi*3+2);
            float xn0 = 2.f*x0 - 1.f, xn1 = 2.f*x1 - 1.f, xn2 = 2.f*x2 - 1.f;
            int row = warp*8 + pi;
            char* rbase = smem + BY_A1 + row*SA1_B;

            if (act) {
                float gx = (i_of == 2) ? xn1 : xn0;
                float gy = (i_of == 0) ? xn1 : xn2;
                float gl = (i_of == 0) ? xn2 : ((i_of == 1) ? xn1 : xn0);
                float px = (gx + 1.f) * 0.5f * 511.f;
                float py = (gy + 1.f) * 0.5f * 511.f;
                float pl = (gl + 1.f) * 0.5f * 511.f;
                int ix = min(max((int)floorf(px), 0), 510);
                int iy = min(max((int)floorf(py), 0), 510);
                int il = min(max((int)floorf(pl), 0), 510);
                float wx = px - ix, wy = py - iy, wl = pl - il;
                const __half* pb = g_planesTh + ((long)((i_of*GRIDSZ + iy)*GRIDSZ) + ix)*NC + cj;
                const __half* lb = g_linesTh + (i_of*GRIDSZ + il)*NC + cj;
                uint2 u00 = *(const uint2*)pb;
                uint2 u01 = *(const uint2*)(pb + NC);
                uint2 u10 = *(const uint2*)(pb + GRIDSZ*NC);
                uint2 u11 = *(const uint2*)(pb + GRIDSZ*NC + NC);
                uint2 ul0 = *(const uint2*)lb;
                uint2 ul1 = *(const uint2*)(lb + NC);
                float2 f00a = __half22float2(*(__half2*)&u00.x), f00b = __half22float2(*(__half2*)&u00.y);
                float2 f01a = __half22float2(*(__half2*)&u01.x), f01b = __half22float2(*(__half2*)&u01.y);
                float2 f10a = __half22float2(*(__half2*)&u10.x), f10b = __half22float2(*(__half2*)&u10.y);
                float2 f11a = __half22float2(*(__half2*)&u11.x), f11b = __half22float2(*(__half2*)&u11.y);
                float2 l0a  = __half22float2(*(__half2*)&ul0.x), l0b  = __half22float2(*(__half2*)&ul0.y);
                float2 l1a  = __half22float2(*(__half2*)&ul1.x), l1b  = __half22float2(*(__half2*)&ul1.y);
                float rx, ry, rz, rw;
                float fx0, fx1;
                fx0 = f00a.x + wx*(f01a.x - f00a.x); fx1 = f10a.x + wx*(f11a.x - f10a.x);
                rx = (fx0 + wy*(fx1 - fx0)) * (l0a.x + wl*(l1a.x - l0a.x));
                fx0 = f00a.y + wx*(f01a.y - f00a.y); fx1 = f10a.y + wx*(f11a.y - f10a.y);
                ry = (fx0 + wy*(fx1 - fx0)) * (l0a.y + wl*(l1a.y - l0a.y));
                fx0 = f00b.x + wx*(f01b.x - f00b.x); fx1 = f10b.x + wx*(f11b.x - f10b.x);
                rz = (fx0 + wy*(fx1 - fx0)) * (l0b.x + wl*(l1b.x - l0b.x));
                fx0 = f00b.y + wx*(f01b.y - f00b.y); fx1 = f10b.y + wx*(f11b.y - f10b.y);
                rw = (fx0 + wy*(fx1 - fx0)) * (l0b.y + wl*(l1b.y - l0b.y));
                *(__half2*)(rbase + fcol*2)     = __floats2half2_rn(rx, ry);
                *(__half2*)(rbase + fcol*2 + 4) = __floats2half2_rn(rz, rw);
            }

            float pv;
            if (lane < 3) pv = (lane == 0) ? xn0 : ((lane == 1) ? xn1 : xn2);
            else if (lane < 21) {
                int j = lane - 3, f = j / 6, rr = j - 6*f, d = rr % 3;
                float xv = ((d == 0) ? xn0 : ((d == 1) ? xn1 : xn2)) * (float)(1 << f);
                pv = (rr < 3) ? __sinf(xv) : __cosf(xv);
            } else pv = 0.f;
            if (pcol < K1PAD)
                *(__half*)(rbase + pcol*2) = __float2half_rn(pv);
        }
    }

    cp_wait0();
    __syncthreads();

    // ================= GEMM1: 8 warps = 2m(32 rows) x 4n(64 cols), ldmatrix =================
    const int mt = warp & 1;
    const int nq = warp >> 1;          // 0..3
    const int arow = mt * 32;

    const int lrow  = (lane & 7) + ((lane >> 3) & 1) * 8;
    const int koffb = (lane >> 4) * 16;

    const uint32_t aAddr1 = smem_u32 + BY_A1 + (uint32_t)(arow + lrow)*SA1_B + koffb;
    const uint32_t bAddr1 = smem_u32 + BY_W1 + (uint32_t)(nq*64 + lrow)*SA1_B + koffb;
    const uint32_t aT1 = smem_u32 + BY_A1 + (uint32_t)(arow + lrow)*SA1_B + 256;
    const uint32_t bT1 = smem_u32 + BY_W1 + (uint32_t)(nq*64 + lrow)*SA1_B + 256;

    float acc[2][8][4];
    #pragma unroll
    for (int i = 0; i < 2; i++)
        #pragma unroll
        for (int j = 0; j < 8; j++)
            #pragma unroll
            for (int q = 0; q < 4; q++) acc[i][j][q] = 0.f;

    #pragma unroll
    for (int ks = 0; ks < 8; ks++) {
        unsigned a0, a1, a2, a3, a4, a5, a6, a7;
        ldsm_x4(a0, a1, a2, a3, aAddr1 + ks*32);
        ldsm_x4(a4, a5, a6, a7, aAddr1 + 16*SA1_B + ks*32);
        #pragma unroll
        for (int p = 0; p < 4; p++) {
            unsigned b0, b1x, b2x, b3;
            ldsm_x4(b0, b1x, b2x, b3, bAddr1 + (uint32_t)p*16*SA1_B + ks*32);
            mma_f16_k16(acc[0][2*p],   a0, a1, a2, a3, b0, b2x);
            mma_f16_k16(acc[0][2*p+1], a0, a1, a2, a3, b1x, b3);
            mma_f16_k16(acc[1][2*p],   a4, a5, a6, a7, b0, b2x);
            mma_f16_k16(acc[1][2*p+1], a4, a5, a6, a7, b1x, b3);
        }
    }
    {   // k8 tail: k = 128..135
        unsigned a0, a1, a4, a5;
        ldsm_x2(a0, a1, aT1);
        ldsm_x2(a4, a5, aT1 + 16*SA1_B);
        #pragma unroll
        for (int p = 0; p < 4; p++) {
            unsigned b0, b1x;
            ldsm_x2(b0, b1x, bT1 + (uint32_t)p*16*SA1_B);
            mma_f16_k8(acc[0][2*p],   a0, a1, b0);
            mma_f16_k8(acc[0][2*p+1], a0, a1, b1x);
            mma_f16_k8(acc[1][2*p],   a4, a5, b0);
            mma_f16_k8(acc[1][2*p+1], a4, a5, b1x);
        }
    }

    __syncthreads();   // all W1/A1 reads done

    // stage W2 image (144 x 528 B = 4752 x 16B)
    for (int idx = tid; idx < 4752; idx += NTHREADS)
        cp16(smem_u32 + BY_W2 + (uint32_t)idx*16u, (const char*)g_W2h + idx*16);
    cp_commit();

    // epilogue 1: half2 softplus (bias folded) -> fp16 A2 (stride 528B)
    #pragma unroll
    for (int mf = 0; mf < 2; mf++) {
        #pragma unroll
        for (int nf = 0; nf < 8; nf++) {
            int col = nq*64 + nf*8 + 2*t;
            __half2 hb = hb1[col >> 1];
            int row0 = arow + mf*16 + g;
            __half2 z01 = __floats2half2_rn(acc[mf][nf][0], acc[mf][nf][1]);
            __half2 z23 = __floats2half2_rn(acc[mf][nf][2], acc[mf][nf][3]);
            *(__half2*)(smem + BY_A2 + row0*SA2_B + col*2)     = softplus2(z01, hb);
            *(__half2*)(smem + BY_A2 + (row0+8)*SA2_B + col*2) = softplus2(z23, hb);
        }
    }

    cp_wait0();
    __syncthreads();

    // ================= GEMM2: 8 warps = 4m(16 rows) x 2n(72 cols), ldmatrix =================
    const int mt2 = warp & 3;
    const int nh2 = warp >> 2;         // 0..1
    const int arow2 = mt2 * 16;

    const uint32_t aAddr2 = smem_u32 + BY_A2 + (uint32_t)(arow2 + lrow)*SA2_B + koffb;
    const uint32_t bAddr2 = smem_u32 + BY_W2 + (uint32_t)(nh2*72 + lrow)*SA2_B + koffb;
    const uint32_t bAddr2e = smem_u32 + BY_W2 + (uint32_t)(nh2*72 + 64 + (lane & 7))*SA2_B
                           + ((lane >> 3) & 1) * 16;

    float acc2[9][4];
    #pragma unroll
    for (int j = 0; j < 9; j++)
        #pragma unroll
        for (int q = 0; q < 4; q++) acc2[j][q] = 0.f;

    #pragma unroll
    for (int ks = 0; ks < 16; ks++) {
        unsigned a0, a1, a2, a3;
        ldsm_x4(a0, a1, a2, a3, aAddr2 + ks*32);
        #pragma unroll
        for (int p = 0; p < 4; p++) {
            unsigned b0, b1x, b2x, b3;
            ldsm_x4(b0, b1x, b2x, b3, bAddr2 + (uint32_t)p*16*SA2_B + ks*32);
            mma_f16_k16(acc2[2*p],   a0, a1, a2, a3, b0, b2x);
            mma_f16_k16(acc2[2*p+1], a0, a1, a2, a3, b1x, b3);
        }
        {
            unsigned b0, b1x;
            ldsm_x2(b0, b1x, bAddr2e + ks*32);
            mma_f16_k16(acc2[8], a0, a1, a2, a3, b0, b1x);
        }
    }

    // epilogue 2: bias + streaming store
    #pragma unroll
    for (int nf = 0; nf < 9; nf++) {
        int col = nh2*72 + nf*8 + 2*t;
        float o0 = acc2[nf][0] + b2s[col];
        float o1 = acc2[nf][1] + b2s[col+1];
        float o2 = acc2[nf][2] + b2s[col];
        float o3 = acc2[nf][3] + b2s[col+1];
        int r0 = (pbase + arow2 + g) * NOUT;
        int r1 = r0 + 8*NOUT;
        if (col < NOUT)     { __stcs(&out[r0 + col], o0);     __stcs(&out[r1 + col], o2); }
        if (col + 1 < NOUT) { __stcs(&out[r0 + col + 1], o1); __stcs(&out[r1 + col + 1], o3); }
    }
}

extern "C" void kernel_launch(void* const* d_in, const int* in_sizes, int n_in,
                              void* d_out, int out_size) {
    const float* xyz    = (const float*)d_in[0];
    const float* planes = (const float*)d_in[1];
    const float* lines  = (const float*)d_in[2];
    const float* W1     = (const float*)d_in[3];
    const float* b1     = (const float*)d_in[4];
    const float* W2     = (const float*)d_in[5];
    const float* b2     = (const float*)d_in[6];
    float* out = (float*)d_out;

    static bool attr_set = false;
    if (!attr_set) {
        cudaFuncSetAttribute(tensosdf_main,
                             cudaFuncAttributeMaxDynamicSharedMemorySize, SMEM_BYTES);
        attr_set = true;
    }

    transpose_planes<<<3072, 256>>>(planes);
    transpose_lines<<<6, 256>>>(lines);
    const int npack = 256*136 + N2PAD*264;
    pack_weights_kernel<<<(npack + 255) / 256, 256>>>(W1, W2);
    tensosdf_main<<<NPTS / TB, NTHREADS, SMEM_BYTES>>>(xyz, b1, b2, out);
}

// round 14
// speedup vs baseline: 1.0345x; 1.0345x over previous
#include <cuda_runtime.h>
#include <cuda_fp16.h>
#include <math.h>
#include <stdint.h>

#define NPTS      524288
#define GRIDSZ    512
#define NC        36
#define KIN       129
#define K1PAD     136
#define HID       256
#define NOUT      129
#define TB        64
#define NTHREADS  256

// ---- smem byte layout (per CTA, 2 CTAs/SM) ----
#define BY_W1   0
#define BY_W2   0
#define BY_A1   76032
#define BY_A2   76032
#define BY_B1S  109824      // f32 table: 100*b1, 256 entries (1024 B)
#define BY_B2S  110848      // f32 b2, padded to 144 (576 B)
#define SMEM_BYTES 111424

#define SA1_B 272         // A1/W1 row stride bytes; 272%128=16 -> ldsm conflict-free
#define SA2_B 528         // A2/W2 row stride bytes; 528%128=16 -> ldsm conflict-free
#define N2PAD 144

__device__ __align__(16) __half g_planesTh[3*GRIDSZ*GRIDSZ*NC]; // [i][y][x][c] fp16
__device__ __align__(16) __half g_linesTh[3*GRIDSZ*NC];         // [i][l][c] fp16
__device__ __align__(16) __half g_W1h[256*136];   // [n][k], fp16, zero-padded k>=129
__device__ __align__(16) __half g_W2h[N2PAD*264]; // [n][k], fp16, zero-padded

// ================= prep kernels =================
__global__ void __launch_bounds__(256) transpose_planes(const float* __restrict__ planes) {
    __shared__ float tile[8][32*37];
    int wid = threadIdx.x >> 5, lane = threadIdx.x & 31;
    int cell0 = (blockIdx.x * 8 + wid) * 32;
    int i = cell0 / (GRIDSZ*GRIDSZ);
    int rem = cell0 - i*GRIDSZ*GRIDSZ;
    int y = rem >> 9, x0 = rem & (GRIDSZ-1);
    const float* src = planes + (long)i*NC*GRIDSZ*GRIDSZ + (long)y*GRIDSZ + x0 + lane;
    float* t = tile[wid];
    #pragma unroll
    for (int c = 0; c < NC; c++) t[lane*37 + c] = src[(long)c*GRIDSZ*GRIDSZ];
    __syncwarp();
    __half2* dst = (__half2*)(g_planesTh + (long)cell0 * NC);
    #pragma unroll
    for (int k = 0; k < 18; k++) {
        int h2i = k*32 + lane;
        int e0 = h2i*2;
        int cc = e0 / NC, c = e0 - cc*NC;
        dst[h2i] = __floats2half2_rn(t[cc*37+c], t[cc*37+c+1]);
    }
}

__global__ void transpose_lines(const float* __restrict__ lines) {
    int t2 = blockIdx.x * blockDim.x + threadIdx.x;
    if (t2 < 3*GRIDSZ) {
        int j = t2 & (GRIDSZ-1), i = t2 >> 9;
        __half* dst = g_linesTh + t2*NC;
        const float* src = lines + (long)i*NC*GRIDSZ + j;
        #pragma unroll
        for (int c = 0; c < NC; c++) dst[c] = __float2half_rn(src[(long)c*GRIDSZ]);
    }
}

__global__ void pack_weights_kernel(const float* __restrict__ W1, const float* __restrict__ W2) {
    int idx = blockIdx.x * blockDim.x + threadIdx.x;
    const int T1 = 256*136;
    const int T2 = N2PAD*264;
    if (idx < T1) {
        int n = idx / 136, k = idx - n*136;
        g_W1h[idx] = (k < KIN) ? __float2half_rn(W1[k*HID + n]) : __float2half_rn(0.f);
    } else if (idx < T1 + T2) {
        int j = idx - T1;
        int n = j / 264, k = j - n*264;
        float v = (k < 256 && n < NOUT) ? W2[k*NOUT + n] : 0.f;
        g_W2h[j] = __float2half_rn(v);
    }
}

// ================= mma / ldmatrix helpers =================
__device__ __forceinline__ void mma_f16_k16(float c[4], unsigned a0, unsigned a1,
                                            unsigned a2, unsigned a3,
                                            unsigned b0, unsigned b1) {
    asm volatile(
        "mma.sync.aligned.m16n8k16.row.col.f32.f16.f16.f32 "
        "{%0,%1,%2,%3},{%4,%5,%6,%7},{%8,%9},{%0,%1,%2,%3};"
        : "+f"(c[0]), "+f"(c[1]), "+f"(c[2]), "+f"(c[3])
        : "r"(a0), "r"(a1), "r"(a2), "r"(a3), "r"(b0), "r"(b1));
}
__device__ __forceinline__ void mma_f16_k8(float c[4], unsigned a0, unsigned a1, unsigned b0) {
    asm volatile(
        "mma.sync.aligned.m16n8k8.row.col.f32.f16.f16.f32 "
        "{%0,%1,%2,%3},{%4,%5},{%6},{%0,%1,%2,%3};"
        : "+f"(c[0]), "+f"(c[1]), "+f"(c[2]), "+f"(c[3])
        : "r"(a0), "r"(a1), "r"(b0));
}
__device__ __forceinline__ void ldsm_x4(unsigned& r0, unsigned& r1, unsigned& r2, unsigned& r3,
                                        uint32_t a) {
    asm volatile("ldmatrix.sync.aligned.m8n8.x4.shared.b16 {%0,%1,%2,%3}, [%4];"
                 : "=r"(r0), "=r"(r1), "=r"(r2), "=r"(r3) : "r"(a));
}
__device__ __forceinline__ void ldsm_x2(unsigned& r0, unsigned& r1, uint32_t a) {
    asm volatile("ldmatrix.sync.aligned.m8n8.x2.shared.b16 {%0,%1}, [%2];"
                 : "=r"(r0), "=r"(r1) : "r"(a));
}

// f32 softplus with pre-scaled bias: y = 100*z + b100
__device__ __forceinline__ float softplus100b(float z, float b100) {
    float y = fmaf(z, 100.f, b100);
    float e = __expf(-fabsf(y));
    return 0.01f * (fmaxf(y, 0.f) + __logf(1.f + e));
}

__device__ __forceinline__ void cp16(uint32_t dst, const void* src) {
    asm volatile("cp.async.cg.shared.global [%0], [%1], 16;" :: "r"(dst), "l"(src));
}
__device__ __forceinline__ void cp_commit() { asm volatile("cp.async.commit_group;"); }
__device__ __forceinline__ void cp_wait0()  { asm volatile("cp.async.wait_group 0;" ::: "memory"); }

// ================= main fused kernel (2 CTAs/SM) =================
__global__ void __launch_bounds__(NTHREADS, 2)
tensosdf_main(const float* __restrict__ xyz,
              const float* __restrict__ b1, const float* __restrict__ b2,
              float* __restrict__ out) {
    extern __shared__ char smem[];
    const uint32_t smem_u32 = (uint32_t)__cvta_generic_to_shared(smem);
    float* b1s = (float*)(smem + BY_B1S);   // 100*b1
    float* b2s = (float*)(smem + BY_B2S);

    const int tid  = threadIdx.x;
    const int lane = tid & 31;
    const int warp = tid >> 5;            // 0..7
    const int pbase = blockIdx.x * TB;
    const int g = lane >> 2;
    const int t = lane & 3;

    // ---- biases ----
    b1s[tid] = 100.f * b1[tid];
    if (tid < N2PAD) b2s[tid] = (tid < NOUT) ? b2[tid] : 0.f;

    // ---- stage W1 image (69632 B = 4352 x 16B), overlaps gather ----
    for (int idx = tid; idx < 4352; idx += NTHREADS)
        cp16(smem_u32 + BY_W1 + (uint32_t)idx*16u, (const char*)g_W1h + idx*16);
    cp_commit();

    // ---- gather: warp handles 8 points, fp16 tables, writes fp16 A1 ----
    {
        const unsigned FULL = 0xffffffffu;
        float vload = 0.f;
        int base3 = (pbase + warp*8)*3;
        if (lane < 24) vload = xyz[base3 + lane];

        const int i_of = (lane < 9) ? 0 : ((lane < 18) ? 1 : 2);
        const int cj = (lane - i_of*9) * 4;
        const bool act = lane < 27;
        const int fcol = i_of*NC + cj;
        const int pcol = 108 + lane;

        #pragma unroll
        for (int pi = 0; pi < 8; pi++) {
            float x0 = __shfl_sync(FULL, vload, pi*3+0);
            float x1 = __shfl_sync(FULL, vload, pi*3+1);
            float x2 = __shfl_sync(FULL, vload, pi*3+2);
            float xn0 = 2.f*x0 - 1.f, xn1 = 2.f*x1 - 1.f, xn2 = 2.f*x2 - 1.f;
            int row = warp*8 + pi;
            char* rbase = smem + BY_A1 + row*SA1_B;

            if (act) {
                float gx = (i_of == 2) ? xn1 : xn0;
                float gy = (i_of == 0) ? xn1 : xn2;
                float gl = (i_of == 0) ? xn2 : ((i_of == 1) ? xn1 : xn0);
                float px = (gx + 1.f) * 0.5f * 511.f;
                float py = (gy + 1.f) * 0.5f * 511.f;
                float pl = (gl + 1.f) * 0.5f * 511.f;
                int ix = min(max((int)floorf(px), 0), 510);
                int iy = min(max((int)floorf(py), 0), 510);
                int il = min(max((int)floorf(pl), 0), 510);
                float wx = px - ix, wy = py - iy, wl = pl - il;
                const __half* pb = g_planesTh + ((long)((i_of*GRIDSZ + iy)*GRIDSZ) + ix)*NC + cj;
                const __half* lb = g_linesTh + (i_of*GRIDSZ + il)*NC + cj;
                uint2 u00 = *(const uint2*)pb;
                uint2 u01 = *(const uint2*)(pb + NC);
                uint2 u10 = *(const uint2*)(pb + GRIDSZ*NC);
                uint2 u11 = *(const uint2*)(pb + GRIDSZ*NC + NC);
                uint2 ul0 = *(const uint2*)lb;
                uint2 ul1 = *(const uint2*)(lb + NC);
                float2 f00a = __half22float2(*(__half2*)&u00.x), f00b = __half22float2(*(__half2*)&u00.y);
                float2 f01a = __half22float2(*(__half2*)&u01.x), f01b = __half22float2(*(__half2*)&u01.y);
                float2 f10a = __half22float2(*(__half2*)&u10.x), f10b = __half22float2(*(__half2*)&u10.y);
                float2 f11a = __half22float2(*(__half2*)&u11.x), f11b = __half22float2(*(__half2*)&u11.y);
                float2 l0a  = __half22float2(*(__half2*)&ul0.x), l0b  = __half22float2(*(__half2*)&ul0.y);
                float2 l1a  = __half22float2(*(__half2*)&ul1.x), l1b  = __half22float2(*(__half2*)&ul1.y);
                float rx, ry, rz, rw;
                float fx0, fx1;
                fx0 = f00a.x + wx*(f01a.x - f00a.x); fx1 = f10a.x + wx*(f11a.x - f10a.x);
                rx = (fx0 + wy*(fx1 - fx0)) * (l0a.x + wl*(l1a.x - l0a.x));
                fx0 = f00a.y + wx*(f01a.y - f00a.y); fx1 = f10a.y + wx*(f11a.y - f10a.y);
                ry = (fx0 + wy*(fx1 - fx0)) * (l0a.y + wl*(l1a.y - l0a.y));
                fx0 = f00b.x + wx*(f01b.x - f00b.x); fx1 = f10b.x + wx*(f11b.x - f10b.x);
                rz = (fx0 + wy*(fx1 - fx0)) * (l0b.x + wl*(l1b.x - l0b.x));
                fx0 = f00b.y + wx*(f01b.y - f00b.y); fx1 = f10b.y + wx*(f11b.y - f10b.y);
                rw = (fx0 + wy*(fx1 - fx0)) * (l0b.y + wl*(l1b.y - l0b.y));
                *(__half2*)(rbase + fcol*2)     = __floats2half2_rn(rx, ry);
                *(__half2*)(rbase + fcol*2 + 4) = __floats2half2_rn(rz, rw);
            }

            float pv;
            if (lane < 3) pv = (lane == 0) ? xn0 : ((lane == 1) ? xn1 : xn2);
            else if (lane < 21) {
                int j = lane - 3, f = j / 6, rr = j - 6*f, d = rr % 3;
                float xv = ((d == 0) ? xn0 : ((d == 1) ? xn1 : xn2)) * (float)(1 << f);
                pv = (rr < 3) ? __sinf(xv) : __cosf(xv);
            } else pv = 0.f;
            if (pcol < K1PAD)
                *(__half*)(rbase + pcol*2) = __float2half_rn(pv);
        }
    }

    cp_wait0();
    __syncthreads();

    // ================= GEMM1: 8 warps = 2m(32 rows) x 4n(64 cols), ldmatrix =================
    const int mt = warp & 1;
    const int nq = warp >> 1;          // 0..3
    const int arow = mt * 32;

    const int lrow  = (lane & 7) + ((lane >> 3) & 1) * 8;
    const int koffb = (lane >> 4) * 16;

    const uint32_t aAddr1 = smem_u32 + BY_A1 + (uint32_t)(arow + lrow)*SA1_B + koffb;
    const uint32_t bAddr1 = smem_u32 + BY_W1 + (uint32_t)(nq*64 + lrow)*SA1_B + koffb;
    const uint32_t aT1 = smem_u32 + BY_A1 + (uint32_t)(arow + lrow)*SA1_B + 256;
    const uint32_t bT1 = smem_u32 + BY_W1 + (uint32_t)(nq*64 + lrow)*SA1_B + 256;

    float acc[2][8][4];
    #pragma unroll
    for (int i = 0; i < 2; i++)
        #pragma unroll
        for (int j = 0; j < 8; j++)
            #pragma unroll
            for (int q = 0; q < 4; q++) acc[i][j][q] = 0.f;

    #pragma unroll
    for (int ks = 0; ks < 8; ks++) {
        unsigned a0, a1, a2, a3, a4, a5, a6, a7;
        ldsm_x4(a0, a1, a2, a3, aAddr1 + ks*32);
        ldsm_x4(a4, a5, a6, a7, aAddr1 + 16*SA1_B + ks*32);
        #pragma unroll
        for (int p = 0; p < 4; p++) {
            unsigned b0, b1x, b2x, b3;
            ldsm_x4(b0, b1x, b2x, b3, bAddr1 + (uint32_t)p*16*SA1_B + ks*32);
            mma_f16_k16(acc[0][2*p],   a0, a1, a2, a3, b0, b2x);
            mma_f16_k16(acc[0][2*p+1], a0, a1, a2, a3, b1x, b3);
            mma_f16_k16(acc[1][2*p],   a4, a5, a6, a7, b0, b2x);
            mma_f16_k16(acc[1][2*p+1], a4, a5, a6, a7, b1x, b3);
        }
    }
    {   // k8 tail: k = 128..135
        unsigned a0, a1, a4, a5;
        ldsm_x2(a0, a1, aT1);
        ldsm_x2(a4, a5, aT1 + 16*SA1_B);
        #pragma unroll
        for (int p = 0; p < 4; p++) {
            unsigned b0, b1x;
            ldsm_x2(b0, b1x, bT1 + (uint32_t)p*16*SA1_B);
            mma_f16_k8(acc[0][2*p],   a0, a1, b0);
            mma_f16_k8(acc[0][2*p+1], a0, a1, b1x);
            mma_f16_k8(acc[1][2*p],   a4, a5, b0);
            mma_f16_k8(acc[1][2*p+1], a4, a5, b1x);
        }
    }

    __syncthreads();   // all W1/A1 reads done

    // stage W2 image (144 x 528 B = 4752 x 16B)
    for (int idx = tid; idx < 4752; idx += NTHREADS)
        cp16(smem_u32 + BY_W2 + (uint32_t)idx*16u, (const char*)g_W2h + idx*16);
    cp_commit();

    // epilogue 1: f32 softplus (bias pre-scaled) -> fp16 A2 (stride 528B)
    #pragma unroll
    for (int mf = 0; mf < 2; mf++) {
        #pragma unroll
        for (int nf = 0; nf < 8; nf++) {
            int col = nq*64 + nf*8 + 2*t;
            float2 bb = *(float2*)&b1s[col];
            int row0 = arow + mf*16 + g;
            float r0 = softplus100b(acc[mf][nf][0], bb.x);
            float r1 = softplus100b(acc[mf][nf][1], bb.y);
            float r2 = softplus100b(acc[mf][nf][2], bb.x);
            float r3 = softplus100b(acc[mf][nf][3], bb.y);
            *(__half2*)(smem + BY_A2 + row0*SA2_B + col*2)     = __floats2half2_rn(r0, r1);
            *(__half2*)(smem + BY_A2 + (row0+8)*SA2_B + col*2) = __floats2half2_rn(r2, r3);
        }
    }

    cp_wait0();
    __syncthreads();

    // ================= GEMM2: 8 warps = 4m(16 rows) x 2n(72 cols), ldmatrix =================
    const int mt2 = warp & 3;
    const int nh2 = warp >> 2;         // 0..1
    const int arow2 = mt2 * 16;

    const uint32_t aAddr2 = smem_u32 + BY_A2 + (uint32_t)(arow2 + lrow)*SA2_B + koffb;
    const uint32_t bAddr2 = smem_u32 + BY_W2 + (uint32_t)(nh2*72 + lrow)*SA2_B + koffb;
    const uint32_t bAddr2e = smem_u32 + BY_W2 + (uint32_t)(nh2*72 + 64 + (lane & 7))*SA2_B
                           + ((lane >> 3) & 1) * 16;

    float acc2[9][4];
    #pragma unroll
    for (int j = 0; j < 9; j++)
        #pragma unroll
        for (int q = 0; q < 4; q++) acc2[j][q] = 0.f;

    #pragma unroll
    for (int ks = 0; ks < 16; ks++) {
        unsigned a0, a1, a2, a3;
        ldsm_x4(a0, a1, a2, a3, aAddr2 + ks*32);
        #pragma unroll
        for (int p = 0; p < 4; p++) {
            unsigned b0, b1x, b2x, b3;
            ldsm_x4(b0, b1x, b2x, b3, bAddr2 + (uint32_t)p*16*SA2_B + ks*32);
            mma_f16_k16(acc2[2*p],   a0, a1, a2, a3, b0, b2x);
            mma_f16_k16(acc2[2*p+1], a0, a1, a2, a3, b1x, b3);
        }
        {
            unsigned b0, b1x;
            ldsm_x2(b0, b1x, bAddr2e + ks*32);
            mma_f16_k16(acc2[8], a0, a1, a2, a3, b0, b1x);
        }
    }

    // epilogue 2: bias + streaming store
    #pragma unroll
    for (int nf = 0; nf < 9; nf++) {
        int col = nh2*72 + nf*8 + 2*t;
        float2 bb = *(float2*)&b2s[col];
        float o0 = acc2[nf][0] + bb.x;
        float o1 = acc2[nf][1] + bb.y;
        float o2 = acc2[nf][2] + bb.x;
        float o3 = acc2[nf][3] + bb.y;
        int r0 = (pbase + arow2 + g) * NOUT;
        int r1 = r0 + 8*NOUT;
        if (col < NOUT)     { __stcs(&out[r0 + col], o0);     __stcs(&out[r1 + col], o2); }
        if (col + 1 < NOUT) { __stcs(&out[r0 + col + 1], o1); __stcs(&out[r1 + col + 1], o3); }
    }
}

extern "C" void kernel_launch(void* const* d_in, const int* in_sizes, int n_in,
                              void* d_out, int out_size) {
    const float* xyz    = (const float*)d_in[0];
    const float* planes = (const float*)d_in[1];
    const float* lines  = (const float*)d_in[2];
    const float* W1     = (const float*)d_in[3];
    const float* b1     = (const float*)d_in[4];
    const float* W2     = (const float*)d_in[5];
    const float* b2     = (const float*)d_in[6];
    float* out = (float*)d_out;

    static bool attr_set = false;
    if (!attr_set) {
        cudaFuncSetAttribute(tensosdf_main,
                             cudaFuncAttributeMaxDynamicSharedMemorySize, SMEM_BYTES);
        attr_set = true;
    }

    transpose_planes<<<3072, 256>>>(planes);
    transpose_lines<<<6, 256>>>(lines);
    const int npack = 256*136 + N2PAD*264;
    pack_weights_kernel<<<(npack + 255) / 256, 256>>>(W1, W2);
    tensosdf_main<<<NPTS / TB, NTHREADS, SMEM_BYTES>>>(xyz, b1, b2, out);
}

// round 15
// speedup vs baseline: 1.1107x; 1.0737x over previous
#include <cuda_runtime.h>
#include <cuda_fp16.h>
#include <math.h>
#include <stdint.h>

#define NPTS      524288
#define GRIDSZ    512
#define NC        36
#define KIN       129
#define HID       256
#define NOUT      129
#define TB        64
#define NTHREADS  256

// ---- smem byte layout (per CTA, 3 CTAs/SM) ----
// W1 chunk dbl buf [0,40960) ; W1 tail [40960,45056) ; A1 [45056,62464)
// after GEMM1: A2 [0,33792) ; W2 chunk dbl buf [33792,56832)
// biases: b1s(100*b1) [62464,63488) ; b2s [63488,64064)
#define BY_WC   0
#define CH1_SZ  20480      // 256 rows x 80 B
#define BY_A2   0
#define BY_W2C  33792
#define CH2_SZ  11520      // 144 rows x 80 B
#define BY_WT   40960      // 256 rows x 16 B
#define BY_A1   45056
#define BY_B1S  62464
#define BY_B2S  63488
#define SMEM_BYTES 64064

#define SWC_B 80          // chunk row stride; 20r%32 distinct -> ldsm conflict-free
#define SA1_B 272         // A1 row stride; 272%128=16 -> conflict-free
#define SA2_B 528         // A2 row stride
#define N2PAD 144

__device__ __align__(16) __half g_planesTh[3*GRIDSZ*GRIDSZ*NC]; // [i][y][x][c]
__device__ __align__(16) __half g_linesTh[3*GRIDSZ*NC];
__device__ __align__(16) __half g_W1c[4*256*32];  // [chunk][n][k'] k=0..127
__device__ __align__(16) __half g_W1t[256*8];     // [n][k'] k=128..135 (zero-padded)
__device__ __align__(16) __half g_W2c[8*144*32];  // [chunk][n][k'] n zero-padded >=129

// ================= prep kernels =================
__global__ void __launch_bounds__(256) transpose_planes(const float* __restrict__ planes) {
    __shared__ float tile[8][32*37];
    int wid = threadIdx.x >> 5, lane = threadIdx.x & 31;
    int cell0 = (blockIdx.x * 8 + wid) * 32;
    int i = cell0 / (GRIDSZ*GRIDSZ);
    int rem = cell0 - i*GRIDSZ*GRIDSZ;
    int y = rem >> 9, x0 = rem & (GRIDSZ-1);
    const float* src = planes + (long)i*NC*GRIDSZ*GRIDSZ + (long)y*GRIDSZ + x0 + lane;
    float* t = tile[wid];
    #pragma unroll
    for (int c = 0; c < NC; c++) t[lane*37 + c] = src[(long)c*GRIDSZ*GRIDSZ];
    __syncwarp();
    __half2* dst = (__half2*)(g_planesTh + (long)cell0 * NC);
    #pragma unroll
    for (int k = 0; k < 18; k++) {
        int h2i = k*32 + lane;
        int e0 = h2i*2;
        int cc = e0 / NC, c = e0 - cc*NC;
        dst[h2i] = __floats2half2_rn(t[cc*37+c], t[cc*37+c+1]);
    }
}

__global__ void transpose_lines(const float* __restrict__ lines) {
    int t2 = blockIdx.x * blockDim.x + threadIdx.x;
    if (t2 < 3*GRIDSZ) {
        int j = t2 & (GRIDSZ-1), i = t2 >> 9;
        __half* dst = g_linesTh + t2*NC;
        const float* src = lines + (long)i*NC*GRIDSZ + j;
        #pragma unroll
        for (int c = 0; c < NC; c++) dst[c] = __float2half_rn(src[(long)c*GRIDSZ]);
    }
}

__global__ void pack_weights_kernel(const float* __restrict__ W1, const float* __restrict__ W2) {
    int idx = blockIdx.x * blockDim.x + threadIdx.x;
    const int T1 = 4*256*32;            // 32768
    const int T2 = 256*8;               // 2048
    const int T3 = 8*144*32;            // 36864
    if (idx < T1) {
        int c = idx >> 13, rem = idx & 8191;
        int n = rem >> 5, kp = rem & 31;
        int k = c*32 + kp;              // 0..127 < KIN
        g_W1c[idx] = __float2half_rn(W1[k*HID + n]);
    } else if (idx < T1 + T2) {
        int j = idx - T1;
        int n = j >> 3, kp = j & 7;
        int k = 128 + kp;
        g_W1t[j] = (k < KIN) ? __float2half_rn(W1[k*HID + n]) : __float2half_rn(0.f);
    } else if (idx < T1 + T2 + T3) {
        int j = idx - T1 - T2;
        int c = j / 4608, r = j - c*4608;
        int n = r >> 5, kp = r & 31;
        int k = c*32 + kp;
        float v = (n < NOUT) ? W2[k*NOUT + n] : 0.f;
        g_W2c[j] = __float2half_rn(v);
    }
}

// ================= mma / ldmatrix helpers =================
__device__ __forceinline__ void mma_f16_k16(float c[4], unsigned a0, unsigned a1,
                                            unsigned a2, unsigned a3,
                                            unsigned b0, unsigned b1) {
    asm volatile(
        "mma.sync.aligned.m16n8k16.row.col.f32.f16.f16.f32 "
        "{%0,%1,%2,%3},{%4,%5,%6,%7},{%8,%9},{%0,%1,%2,%3};"
        : "+f"(c[0]), "+f"(c[1]), "+f"(c[2]), "+f"(c[3])
        : "r"(a0), "r"(a1), "r"(a2), "r"(a3), "r"(b0), "r"(b1));
}
__device__ __forceinline__ void mma_h_k16(unsigned& d0, unsigned& d1,
                                          unsigned a0, unsigned a1, unsigned a2, unsigned a3,
                                          unsigned b0, unsigned b1) {
    asm volatile(
        "mma.sync.aligned.m16n8k16.row.col.f16.f16.f16.f16 "
        "{%0,%1},{%2,%3,%4,%5},{%6,%7},{%0,%1};"
        : "+r"(d0), "+r"(d1)
        : "r"(a0), "r"(a1), "r"(a2), "r"(a3), "r"(b0), "r"(b1));
}
__device__ __forceinline__ void mma_h_k8(unsigned& d0, unsigned& d1,
                                         unsigned a0, unsigned a1, unsigned b0) {
    asm volatile(
        "mma.sync.aligned.m16n8k8.row.col.f16.f16.f16.f16 "
        "{%0,%1},{%2,%3},{%4},{%0,%1};"
        : "+r"(d0), "+r"(d1) : "r"(a0), "r"(a1), "r"(b0));
}
__device__ __forceinline__ void ldsm_x4(unsigned& r0, unsigned& r1, unsigned& r2, unsigned& r3,
                                        uint32_t a) {
    asm volatile("ldmatrix.sync.aligned.m8n8.x4.shared.b16 {%0,%1,%2,%3}, [%4];"
                 : "=r"(r0), "=r"(r1), "=r"(r2), "=r"(r3) : "r"(a));
}
__device__ __forceinline__ void ldsm_x2(unsigned& r0, unsigned& r1, uint32_t a) {
    asm volatile("ldmatrix.sync.aligned.m8n8.x2.shared.b16 {%0,%1}, [%2];"
                 : "=r"(r0), "=r"(r1) : "r"(a));
}

__device__ __forceinline__ float softplus100b(float z, float b100) {
    float y = fmaf(z, 100.f, b100);
    float e = __expf(-fabsf(y));
    return 0.01f * (fmaxf(y, 0.f) + __logf(1.f + e));
}
__device__ __forceinline__ void cp16(uint32_t dst, const void* src) {
    asm volatile("cp.async.cg.shared.global [%0], [%1], 16;" :: "r"(dst), "l"(src));
}
__device__ __forceinline__ void cp_commit() { asm volatile("cp.async.commit_group;"); }
__device__ __forceinline__ void cp_wait0()  { asm volatile("cp.async.wait_group 0;" ::: "memory"); }

// ================= main fused kernel (3 CTAs/SM) =================
__global__ void __launch_bounds__(NTHREADS, 3)
tensosdf_main(const float* __restrict__ xyz,
              const float* __restrict__ b1, const float* __restrict__ b2,
              float* __restrict__ out) {
    extern __shared__ char smem[];
    const uint32_t smem_u32 = (uint32_t)__cvta_generic_to_shared(smem);
    float* b1s = (float*)(smem + BY_B1S);   // 100*b1
    float* b2s = (float*)(smem + BY_B2S);

    const int tid  = threadIdx.x;
    const int lane = tid & 31;
    const int warp = tid >> 5;            // 0..7
    const int pbase = blockIdx.x * TB;
    const int g = lane >> 2;
    const int t = lane & 3;

    // ---- biases ----
    b1s[tid] = 100.f * b1[tid];
    if (tid < N2PAD) b2s[tid] = (tid < NOUT) ? b2[tid] : 0.f;

    // ---- prestage W1 chunk 0 + tail (overlaps gather) ----
    for (int idx = tid; idx < 1024; idx += NTHREADS) {
        int n = idx >> 2, p = idx & 3;
        cp16(smem_u32 + BY_WC + (uint32_t)(n*SWC_B + p*16),
             (const char*)g_W1c + n*64 + p*16);
    }
    for (int idx = tid; idx < 256; idx += NTHREADS)
        cp16(smem_u32 + BY_WT + (uint32_t)idx*16u, (const char*)g_W1t + idx*16);
    cp_commit();

    // ---- gather: warp handles 8 points, fp16 tables, writes fp16 A1 ----
    {
        const unsigned FULL = 0xffffffffu;
        float vload = 0.f;
        int base3 = (pbase + warp*8)*3;
        if (lane < 24) vload = xyz[base3 + lane];

        const int i_of = (lane < 9) ? 0 : ((lane < 18) ? 1 : 2);
        const int cj = (lane - i_of*9) * 4;
        const bool act = lane < 27;
        const int fcol = i_of*NC + cj;
        const int pcol = 108 + lane;

        #pragma unroll
        for (int pi = 0; pi < 8; pi++) {
            float x0 = __shfl_sync(FULL, vload, pi*3+0);
            float x1 = __shfl_sync(FULL, vload, pi*3+1);
            float x2 = __shfl_sync(FULL, vload, pi*3+2);
            float xn0 = 2.f*x0 - 1.f, xn1 = 2.f*x1 - 1.f, xn2 = 2.f*x2 - 1.f;
            int row = warp*8 + pi;
            char* rbase = smem + BY_A1 + row*SA1_B;

            if (act) {
                float gx = (i_of == 2) ? xn1 : xn0;
                float gy = (i_of == 0) ? xn1 : xn2;
                float gl = (i_of == 0) ? xn2 : ((i_of == 1) ? xn1 : xn0);
                float px = (gx + 1.f) * 0.5f * 511.f;
                float py = (gy + 1.f) * 0.5f * 511.f;
                float pl = (gl + 1.f) * 0.5f * 511.f;
                int ix = min(max((int)floorf(px), 0), 510);
                int iy = min(max((int)floorf(py), 0), 510);
                int il = min(max((int)floorf(pl), 0), 510);
                float wx = px - ix, wy = py - iy, wl = pl - il;
                const __half* pb = g_planesTh + ((long)((i_of*GRIDSZ + iy)*GRIDSZ) + ix)*NC + cj;
                const __half* lb = g_linesTh + (i_of*GRIDSZ + il)*NC + cj;
                uint2 u00 = *(const uint2*)pb;
                uint2 u01 = *(const uint2*)(pb + NC);
                uint2 u10 = *(const uint2*)(pb + GRIDSZ*NC);
                uint2 u11 = *(const uint2*)(pb + GRIDSZ*NC + NC);
                uint2 ul0 = *(const uint2*)lb;
                uint2 ul1 = *(const uint2*)(lb + NC);
                float2 f00a = __half22float2(*(__half2*)&u00.x), f00b = __half22float2(*(__half2*)&u00.y);
                float2 f01a = __half22float2(*(__half2*)&u01.x), f01b = __half22float2(*(__half2*)&u01.y);
                float2 f10a = __half22float2(*(__half2*)&u10.x), f10b = __half22float2(*(__half2*)&u10.y);
                float2 f11a = __half22float2(*(__half2*)&u11.x), f11b = __half22float2(*(__half2*)&u11.y);
                float2 l0a  = __half22float2(*(__half2*)&ul0.x), l0b  = __half22float2(*(__half2*)&ul0.y);
                float2 l1a  = __half22float2(*(__half2*)&ul1.x), l1b  = __half22float2(*(__half2*)&ul1.y);
                float rx, ry, rz, rw;
                float fx0, fx1;
                fx0 = f00a.x + wx*(f01a.x - f00a.x); fx1 = f10a.x + wx*(f11a.x - f10a.x);
                rx = (fx0 + wy*(fx1 - fx0)) * (l0a.x + wl*(l1a.x - l0a.x));
                fx0 = f00a.y + wx*(f01a.y - f00a.y); fx1 = f10a.y + wx*(f11a.y - f10a.y);
                ry = (fx0 + wy*(fx1 - fx0)) * (l0a.y + wl*(l1a.y - l0a.y));
                fx0 = f00b.x + wx*(f01b.x - f00b.x); fx1 = f10b.x + wx*(f11b.x - f10b.x);
                rz = (fx0 + wy*(fx1 - fx0)) * (l0b.x + wl*(l1b.x - l0b.x));
                fx0 = f00b.y + wx*(f01b.y - f00b.y); fx1 = f10b.y + wx*(f11b.y - f10b.y);
                rw = (fx0 + wy*(fx1 - fx0)) * (l0b.y + wl*(l1b.y - l0b.y));
                *(__half2*)(rbase + fcol*2)     = __floats2half2_rn(rx, ry);
                *(__half2*)(rbase + fcol*2 + 4) = __floats2half2_rn(rz, rw);
            }

            float pv;
            if (lane < 3) pv = (lane == 0) ? xn0 : ((lane == 1) ? xn1 : xn2);
            else if (lane < 21) {
                int j = lane - 3, f = j / 6, rr = j - 6*f, d = rr % 3;
                float xv = ((d == 0) ? xn0 : ((d == 1) ? xn1 : xn2)) * (float)(1 << f);
                pv = (rr < 3) ? __sinf(xv) : __cosf(xv);
            } else pv = 0.f;
            if (pcol < 136)
                *(__half*)(rbase + pcol*2) = __float2half_rn(pv);
        }
    }

    cp_wait0();
    __syncthreads();

    // ================= GEMM1: 8 warps = 2m(32) x 4n(64), chunked W1, fp16 acc ==========
    const int mt = warp & 1;
    const int nq = warp >> 1;          // 0..3
    const int arow = mt * 32;

    const int lrow  = (lane & 7) + ((lane >> 3) & 1) * 8;
    const int koffb = (lane >> 4) * 16;

    const uint32_t aAddr1 = smem_u32 + BY_A1 + (uint32_t)(arow + lrow)*SA1_B + koffb;
    const uint32_t bRow1  = (uint32_t)(nq*64 + lrow)*SWC_B + koffb;

    unsigned acch[2][8][2];
    #pragma unroll
    for (int i = 0; i < 2; i++)
        #pragma unroll
        for (int j = 0; j < 8; j++) { acch[i][j][0] = 0u; acch[i][j][1] = 0u; }

    // --- k8 tail first (k=128..135) from WT buffer ---
    {
        unsigned a0, a1, a4, a5;
        ldsm_x2(a0, a1, smem_u32 + BY_A1 + (uint32_t)(arow + lrow)*SA1_B + 256);
        ldsm_x2(a4, a5, smem_u32 + BY_A1 + (uint32_t)(arow + 16 + lrow)*SA1_B + 256);
        #pragma unroll
        for (int p = 0; p < 4; p++) {
            unsigned b0, b1x;
            ldsm_x2(b0, b1x, smem_u32 + BY_WT + (uint32_t)(nq*64 + p*16 + lrow)*16);
            mma_h_k8(acch[0][2*p][0],   acch[0][2*p][1],   a0, a1, b0);
            mma_h_k8(acch[0][2*p+1][0], acch[0][2*p+1][1], a0, a1, b1x);
            mma_h_k8(acch[1][2*p][0],   acch[1][2*p][1],   a4, a5, b0);
            mma_h_k8(acch[1][2*p+1][0], acch[1][2*p+1][1], a4, a5, b1x);
        }
    }

    // --- 4 chunks of 32 k ---
    #pragma unroll 1
    for (int c = 0; c < 4; c++) {
        if (c < 3) {
            uint32_t dbase = smem_u32 + BY_WC + (uint32_t)(((c+1)&1)*CH1_SZ);
            const char* src = (const char*)g_W1c + (c+1)*16384;
            for (int idx = tid; idx < 1024; idx += NTHREADS) {
                int n = idx >> 2, p = idx & 3;
                cp16(dbase + (uint32_t)(n*SWC_B + p*16), src + n*64 + p*16);
            }
            cp_commit();
        }
        uint32_t bufb = smem_u32 + BY_WC + (uint32_t)((c&1)*CH1_SZ);
        #pragma unroll
        for (int ks = 0; ks < 2; ks++) {
            unsigned a0, a1, a2, a3, a4, a5, a6, a7;
            ldsm_x4(a0, a1, a2, a3, aAddr1 + c*64 + ks*32);
            ldsm_x4(a4, a5, a6, a7, aAddr1 + 16*SA1_B + c*64 + ks*32);
            #pragma unroll
            for (int p = 0; p < 4; p++) {
                unsigned b0, b1x, b2x, b3;
                ldsm_x4(b0, b1x, b2x, b3, bufb + bRow1 + (uint32_t)p*16*SWC_B + ks*32);
                mma_h_k16(acch[0][2*p][0],   acch[0][2*p][1],   a0, a1, a2, a3, b0, b2x);
                mma_h_k16(acch[0][2*p+1][0], acch[0][2*p+1][1], a0, a1, a2, a3, b1x, b3);
                mma_h_k16(acch[1][2*p][0],   acch[1][2*p][1],   a4, a5, a6, a7, b0, b2x);
                mma_h_k16(acch[1][2*p+1][0], acch[1][2*p+1][1], a4, a5, a6, a7, b1x, b3);
            }
        }
        if (c < 3) cp_wait0();
        __syncthreads();
    }

    // ---- stage W2 chunk 0 (into [33792,45312), dead region) ----
    for (int idx = tid; idx < 576; idx += NTHREADS) {
        int n = idx >> 2, p = idx & 3;
        cp16(smem_u32 + BY_W2C + (uint32_t)(n*SWC_B + p*16),
             (const char*)g_W2c + n*64 + p*16);
    }
    cp_commit();

    // ---- epilogue 1: softplus -> fp16 A2 ----
    #pragma unroll
    for (int mf = 0; mf < 2; mf++) {
        #pragma unroll
        for (int nf = 0; nf < 8; nf++) {
            int col = nq*64 + nf*8 + 2*t;
            float2 bb = *(float2*)&b1s[col];
            int row0 = arow + mf*16 + g;
            float2 v01 = __half22float2(*(__half2*)&acch[mf][nf][0]);
            float2 v23 = __half22float2(*(__half2*)&acch[mf][nf][1]);
            float r0 = softplus100b(v01.x, bb.x);
            float r1 = softplus100b(v01.y, bb.y);
            float r2 = softplus100b(v23.x, bb.x);
            float r3 = softplus100b(v23.y, bb.y);
            *(__half2*)(smem + BY_A2 + row0*SA2_B + col*2)     = __floats2half2_rn(r0, r1);
            *(__half2*)(smem + BY_A2 + (row0+8)*SA2_B + col*2) = __floats2half2_rn(r2, r3);
        }
    }

    cp_wait0();
    __syncthreads();

    // ================= GEMM2: 8 warps = 4m(16) x 2n(72), chunked W2, f32 acc =========
    const int mt2 = warp & 3;
    const int nh2 = warp >> 2;         // 0..1
    const int arow2 = mt2 * 16;

    const uint32_t aAddr2 = smem_u32 + BY_A2 + (uint32_t)(arow2 + lrow)*SA2_B + koffb;
    const uint32_t bRow2  = (uint32_t)(nh2*72 + lrow)*SWC_B + koffb;
    const uint32_t bRow2e = (uint32_t)(nh2*72 + 64 + (lane & 7))*SWC_B + ((lane >> 3) & 1)*16;

    float acc2[9][4];
    #pragma unroll
    for (int j = 0; j < 9; j++)
        #pragma unroll
        for (int q = 0; q < 4; q++) acc2[j][q] = 0.f;

    #pragma unroll 1
    for (int c = 0; c < 8; c++) {
        if (c < 7) {
            uint32_t dbase = smem_u32 + BY_W2C + (uint32_t)(((c+1)&1)*CH2_SZ);
            const char* src = (const char*)g_W2c + (c+1)*9216;
            for (int idx = tid; idx < 576; idx += NTHREADS) {
                int n = idx >> 2, p = idx & 3;
                cp16(dbase + (uint32_t)(n*SWC_B + p*16), src + n*64 + p*16);
            }
            cp_commit();
        }
        uint32_t bufb = smem_u32 + BY_W2C + (uint32_t)((c&1)*CH2_SZ);
        #pragma unroll
        for (int ks = 0; ks < 2; ks++) {
            unsigned a0, a1, a2, a3;
            ldsm_x4(a0, a1, a2, a3, aAddr2 + c*64 + ks*32);
            #pragma unroll
            for (int p = 0; p < 4; p++) {
                unsigned b0, b1x, b2x, b3;
                ldsm_x4(b0, b1x, b2x, b3, bufb + bRow2 + (uint32_t)p*16*SWC_B + ks*32);
                mma_f16_k16(acc2[2*p],   a0, a1, a2, a3, b0, b2x);
                mma_f16_k16(acc2[2*p+1], a0, a1, a2, a3, b1x, b3);
            }
            {
                unsigned b0, b1x;
                ldsm_x2(b0, b1x, bufb + bRow2e + ks*32);
                mma_f16_k16(acc2[8], a0, a1, a2, a3, b0, b1x);
            }
        }
        if (c < 7) cp_wait0();
        __syncthreads();
    }

    // ---- epilogue 2: bias + streaming store ----
    #pragma unroll
    for (int nf = 0; nf < 9; nf++) {
        int col = nh2*72 + nf*8 + 2*t;
        float2 bb = *(float2*)&b2s[col];
        float o0 = acc2[nf][0] + bb.x;
        float o1 = acc2[nf][1] + bb.y;
        float o2 = acc2[nf][2] + bb.x;
        float o3 = acc2[nf][3] + bb.y;
        int r0 = (pbase + arow2 + g) * NOUT;
        int r1 = r0 + 8*NOUT;
        if (col < NOUT)     { __stcs(&out[r0 + col], o0);     __stcs(&out[r1 + col], o2); }
        if (col + 1 < NOUT) { __stcs(&out[r0 + col + 1], o1); __stcs(&out[r1 + col + 1], o3); }
    }
}

extern "C" void kernel_launch(void* const* d_in, const int* in_sizes, int n_in,
                              void* d_out, int out_size) {
    const float* xyz    = (const float*)d_in[0];
    const float* planes = (const float*)d_in[1];
    const float* lines  = (const float*)d_in[2];
    const float* W1     = (const float*)d_in[3];
    const float* b1     = (const float*)d_in[4];
    const float* W2     = (const float*)d_in[5];
    const float* b2     = (const float*)d_in[6];
    float* out = (float*)d_out;

    static bool attr_set = false;
    if (!attr_set) {
        cudaFuncSetAttribute(tensosdf_main,
                             cudaFuncAttributeMaxDynamicSharedMemorySize, SMEM_BYTES);
        attr_set = true;
    }

    transpose_planes<<<3072, 256>>>(planes);
    transpose_lines<<<6, 256>>>(lines);
    const int npack = 4*256*32 + 256*8 + 8*144*32;
    pack_weights_kernel<<<(npack + 255) / 256, 256>>>(W1, W2);
    tensosdf_main<<<NPTS / TB, NTHREADS, SMEM_BYTES>>>(xyz, b1, b2, out);
}